// round 11
// baseline (speedup 1.0000x reference)
#include <cuda_runtime.h>
#include <cstdint>

// ============================================================================
// out[4096,1000] = core[4096,4096] @ weights[1000,4096]^T   (fp32)
//
// R11 = recombination of measured-best components:
//  - GEMM: R7 version verbatim (per-kt commit groups, per-kt barrier, 4-stage
//    cp.async, cross-phase ks0 fragment prefetch, compile-time stage ring).
//    Measured ~151us @ tensor ~74%. (Super-phases R8/R9 were slower: 159us;
//    pure-LDG R10 much slower: 203us.)
//  - Pack: R8 fused single-launch version (~26us vs 31us for two launches).
// ============================================================================

#define MDIM 4096
#define NDIM 1000
#define KDIM 4096

#define BM 256
#define BN 128
#define BK 32
#define KTILES (KDIM / BK)            // 128
#define STAGES 4
#define THREADS 256

#define A_TILE_BYTES (BM * BK * 4)    // 32768
#define B_TILE_BYTES (BN * BK * 4)    // 16384
#define STAGE_BYTES  (A_TILE_BYTES + B_TILE_BYTES)   // 49152
#define SMEM_BYTES   (STAGES * STAGE_BYTES)          // 196608

// packed scratch: A' = [16 mtiles][128 kt][2048 x 16B], B' = [8 ntiles][128 kt][2048 x 8B]
__device__ uint4 g_Ap[16 * 128 * 2048];   // 64 MB
__device__ uint2 g_Bp[8 * 128 * 2048];    // 16 MB

// ---------------------------------------------------------------------------
__device__ __forceinline__ uint32_t smem_u32(const void* p) {
    uint32_t a;
    asm("{ .reg .u64 t; cvta.to.shared.u64 t, %1; cvt.u32.u64 %0, t; }" : "=r"(a) : "l"(p));
    return a;
}

__device__ __forceinline__ void cp16(uint32_t dst, const void* src) {
    asm volatile("cp.async.cg.shared.global [%0], [%1], 16;"
                 :: "r"(dst), "l"(src) : "memory");
}
#define CP_COMMIT() asm volatile("cp.async.commit_group;" ::: "memory")
#define CP_WAIT1()  asm volatile("cp.async.wait_group 1;"  ::: "memory")
#define CP_WAIT2()  asm volatile("cp.async.wait_group 2;"  ::: "memory")

__device__ __forceinline__ uint32_t f2tf(float f) {
    uint32_t r;
    asm("cvt.rna.tf32.f32 %0, %1;" : "=r"(r) : "f"(f));
    return r;
}

__device__ __forceinline__ void mma_tf32(float c[4],
                                         const uint32_t a[4], const uint32_t b[2]) {
    asm volatile(
        "mma.sync.aligned.m16n8k8.row.col.f32.tf32.tf32.f32 "
        "{%0,%1,%2,%3}, {%4,%5,%6,%7}, {%8,%9}, {%0,%1,%2,%3};"
        : "+f"(c[0]), "+f"(c[1]), "+f"(c[2]), "+f"(c[3])
        : "r"(a[0]), "r"(a[1]), "r"(a[2]), "r"(a[3]), "r"(b[0]), "r"(b[1]));
}

// ---------------------------------------------------------------------------
// Fused pack kernel (R8). Fragment-major layouts:
//   A chunk ((wm*4+t)*4+ks)*32+lane -> 16B quad {A[r,c],A[r+8,c],A[r,c+4],A[r+8,c+4]}
//   B chunk ((wn*8+u)*4+ks)*32+lane -> 8B pair {B[n,c],B[n,c+4]}, n>=1000 zeroed
// Each thread handles 4 consecutive kt. Blocks [0,4096): A. [4096,6144): B.
// ---------------------------------------------------------------------------
__global__ void __launch_bounds__(256) pack_ab_kernel(const float* __restrict__ A,
                                                      const float* __restrict__ B) {
    const uint32_t bid = blockIdx.x;
    const uint32_t tidl = threadIdx.x;
    if (bid < 4096) {
        const uint32_t idx = bid * 256u + tidl;        // [0, 2^20)
        const uint32_t mtile = idx >> 16;
        const uint32_t ktg   = (idx >> 11) & 31u;
        const uint32_t chunk = idx & 2047u;
        const uint32_t lane  = chunk & 31u;
        const uint32_t blk   = chunk >> 5;
        const uint32_t ks    = blk & 3u;
        const uint32_t t     = (blk >> 2) & 3u;
        const uint32_t wm    = blk >> 4;
        const uint32_t r = mtile * 256 + wm * 64 + t * 16 + (lane >> 2);
        const float* rowp = A + (size_t)r * KDIM;
        #pragma unroll
        for (int j = 0; j < 4; j++) {
            const uint32_t kt = ktg * 4 + j;
            const uint32_t c  = kt * 32 + ks * 8 + (lane & 3);
            const float* p = rowp + c;
            uint4 v;
            v.x = f2tf(p[0]);
            v.y = f2tf(p[(size_t)8 * KDIM]);
            v.z = f2tf(p[4]);
            v.w = f2tf(p[(size_t)8 * KDIM + 4]);
            g_Ap[(size_t)(mtile * 128 + kt) * 2048 + chunk] = v;
        }
    } else {
        const uint32_t idx = (bid - 4096u) * 256u + tidl;  // [0, 2^19)
        const uint32_t ntile = idx >> 16;
        const uint32_t ktg   = (idx >> 11) & 31u;
        const uint32_t chunk = idx & 2047u;
        const uint32_t lane  = chunk & 31u;
        const uint32_t blk   = chunk >> 5;
        const uint32_t ks    = blk & 3u;
        const uint32_t u     = (blk >> 2) & 7u;
        const uint32_t wn    = blk >> 5;
        const uint32_t n = ntile * 128 + wn * 64 + u * 8 + (lane >> 2);
        const float* rowp = B + (size_t)n * KDIM;
        #pragma unroll
        for (int j = 0; j < 4; j++) {
            const uint32_t kt = ktg * 4 + j;
            const uint32_t c  = kt * 32 + ks * 8 + (lane & 3);
            uint2 v = make_uint2(0u, 0u);
            if (n < NDIM) {
                const float* p = rowp + c;
                v.x = f2tf(p[0]);
                v.y = f2tf(p[4]);
            }
            g_Bp[(size_t)(ntile * 128 + kt) * 2048 + chunk] = v;
        }
    }
}

// ---------------------------------------------------------------------------
// GEMM: R7 version verbatim.
// ---------------------------------------------------------------------------
__global__ void __launch_bounds__(THREADS, 1)
tol_gemm_tf32(float* __restrict__ C) {         // [4096, 1000]
    extern __shared__ char smem[];
    const int tid  = threadIdx.x;
    const int wid  = tid >> 5;
    const int lane = tid & 31;

    const int mtile = blockIdx.y;
    const int ntile = blockIdx.x;
    const int m0 = mtile * BM;
    const int n0 = ntile * BN;

    const int warp_m = wid >> 1;     // 0..3
    const int warp_n = wid & 1;      // 0..1

    const uint32_t sb = smem_u32(smem);

#define ISSUE_STAGE(kt_, s_) do {                                                \
        const uint32_t soff = (uint32_t)(s_) * STAGE_BYTES;                      \
        const uint4* asrc = g_Ap + ((size_t)(mtile * KTILES + (kt_))) * 2048;    \
        const uint2* bsrc = g_Bp + ((size_t)(ntile * KTILES + (kt_))) * 2048;    \
        _Pragma("unroll")                                                        \
        for (int i = 0; i < 8; i++)                                              \
            cp16(sb + soff + (uint32_t)(tid + i * 256) * 16,                     \
                 asrc + tid + i * 256);                                          \
        _Pragma("unroll")                                                        \
        for (int i = 0; i < 4; i++)                                              \
            cp16(sb + soff + A_TILE_BYTES + (uint32_t)(tid + i * 256) * 16,      \
                 bsrc + (tid + i * 256) * 2);                                    \
    } while (0)

    float acc[4][8][4];
    #pragma unroll
    for (int t = 0; t < 4; t++)
        #pragma unroll
        for (int u = 0; u < 8; u++)
            #pragma unroll
            for (int i = 0; i < 4; i++)
                acc[t][u][i] = 0.0f;

    // prologue: fill STAGES-1 = 3 stages
    #pragma unroll
    for (int p = 0; p < STAGES - 1; p++) {
        ISSUE_STAGE(p, p);
        CP_COMMIT();
    }

    // fragment double buffers
    uint32_t af[2][4][4];
    uint32_t bf[2][8][2];

#define LOAD_FRAG(buf, aS, bS, ksv) do {                                         \
        _Pragma("unroll")                                                        \
        for (int t = 0; t < 4; t++) {                                            \
            uint4 v = (aS)[((warp_m * 4 + t) * 4 + (ksv)) * 32 + lane];          \
            af[buf][t][0] = v.x; af[buf][t][1] = v.y;                            \
            af[buf][t][2] = v.z; af[buf][t][3] = v.w;                            \
        }                                                                        \
        _Pragma("unroll")                                                        \
        for (int u = 0; u < 8; u++) {                                            \
            uint2 w = (bS)[((warp_n * 8 + u) * 4 + (ksv)) * 32 + lane];          \
            bf[buf][u][0] = w.x; bf[buf][u][1] = w.y;                            \
        }                                                                        \
    } while (0)

#define MMA_ALL(buf) do {                                                        \
        _Pragma("unroll")                                                        \
        for (int t = 0; t < 4; t++)                                              \
            _Pragma("unroll")                                                    \
            for (int u = 0; u < 8; u++)                                          \
                mma_tf32(acc[t][u], af[buf][t], bf[buf][u]);                     \
    } while (0)

#define STAGE_A(s_) reinterpret_cast<const uint4*>(smem + (s_) * STAGE_BYTES)
#define STAGE_B(s_) reinterpret_cast<const uint2*>(smem + (s_) * STAGE_BYTES + A_TILE_BYTES)

    // preload buf0 = frag(kt=0, ks=0) from stage 0
    CP_WAIT2();
    __syncthreads();
    LOAD_FRAG(0, STAGE_A(0), STAGE_B(0), 0);

    // One pipeline phase at compile-time stage S. Enters with buf0 holding
    // frag(kt, ks=0); exits with buf0 holding frag(kt+1, ks=0) read from the
    // NEXT stage (complete per wait_group 1; not overwritten until the kt+2
    // refill, which is behind the kt+2 barrier).
#define PHASE(S, kt_) do {                                                       \
        CP_WAIT1();                                                              \
        __syncthreads();                                                         \
        const int kn = (kt_) + STAGES - 1;                                       \
        if (kn < KTILES) ISSUE_STAGE(kn, ((S) + STAGES - 1) & 3);                \
        CP_COMMIT();                                                             \
        const uint4* aS = STAGE_A(S);                                            \
        const uint2* bS = STAGE_B(S);                                            \
        const uint4* aN = STAGE_A(((S) + 1) & 3);                                \
        const uint2* bN = STAGE_B(((S) + 1) & 3);                                \
        LOAD_FRAG(1, aS, bS, 1);  MMA_ALL(0);                                    \
        LOAD_FRAG(0, aS, bS, 2);  MMA_ALL(1);                                    \
        LOAD_FRAG(1, aS, bS, 3);  MMA_ALL(0);                                    \
        LOAD_FRAG(0, aN, bN, 0);  MMA_ALL(1);                                    \
    } while (0)

    for (int kt = 0; kt < KTILES; kt += 4) {
        PHASE(0, kt);
        PHASE(1, kt + 1);
        PHASE(2, kt + 2);
        PHASE(3, kt + 3);
    }

    // ---- epilogue: each warp writes its 64x64 region, guard N edge ----
    #pragma unroll
    for (int t = 0; t < 4; t++) {
        const int gr = m0 + warp_m * 64 + t * 16 + (lane >> 2);
        #pragma unroll
        for (int u = 0; u < 8; u++) {
            const int gc = n0 + warp_n * 64 + u * 8 + (lane & 3) * 2;
            if (gc < NDIM) {   // NDIM even; float2 never straddles the edge
                float2 v0 = make_float2(acc[t][u][0], acc[t][u][1]);
                float2 v1 = make_float2(acc[t][u][2], acc[t][u][3]);
                *reinterpret_cast<float2*>(C + (size_t)gr * NDIM + gc) = v0;
                *reinterpret_cast<float2*>(C + (size_t)(gr + 8) * NDIM + gc) = v1;
            }
        }
    }
}

// ---------------------------------------------------------------------------
extern "C" void kernel_launch(void* const* d_in, const int* in_sizes, int n_in,
                              void* d_out, int out_size) {
    const float* core = (const float*)d_in[0];   // [4096, 16,16,16] = [4096,4096]
    const float* wts  = (const float*)d_in[1];   // [1000, 4096]
    float* out = (float*)d_out;                  // [4096, 1000]

    // fused pack prepass (same stream -> ordered before GEMM)
    pack_ab_kernel<<<6144, 256>>>(core, wts);

    cudaFuncSetAttribute(tol_gemm_tf32,
                         cudaFuncAttributeMaxDynamicSharedMemorySize, SMEM_BYTES);

    dim3 grid(8, 16, 1);   // 128 CTAs = 1 clean wave
    tol_gemm_tf32<<<grid, THREADS, SMEM_BYTES>>>(out);
}

// round 12
// speedup vs baseline: 1.5389x; 1.5389x over previous
#include <cuda_runtime.h>
#include <cstdint>

// ============================================================================
// out[4096,1000] = core[4096,4096] @ weights[1000,4096]^T   (fp32)
//
// R12 = R11 resubmitted as a controlled re-measurement. R11's 269us run shows
// the DVFS signature (duration +45% at CONSTANT tensor-pipe %, i.e. slow
// clocks, not extra stalls). Composition: R7 GEMM (best measured structure:
// per-kt commit groups, per-kt barrier, 4-stage cp.async, cross-phase ks0
// fragment prefetch, compile-time stage ring) + fused single-launch pack.
// ============================================================================

#define MDIM 4096
#define NDIM 1000
#define KDIM 4096

#define BM 256
#define BN 128
#define BK 32
#define KTILES (KDIM / BK)            // 128
#define STAGES 4
#define THREADS 256

#define A_TILE_BYTES (BM * BK * 4)    // 32768
#define B_TILE_BYTES (BN * BK * 4)    // 16384
#define STAGE_BYTES  (A_TILE_BYTES + B_TILE_BYTES)   // 49152
#define SMEM_BYTES   (STAGES * STAGE_BYTES)          // 196608

// packed scratch: A' = [16 mtiles][128 kt][2048 x 16B], B' = [8 ntiles][128 kt][2048 x 8B]
__device__ uint4 g_Ap[16 * 128 * 2048];   // 64 MB
__device__ uint2 g_Bp[8 * 128 * 2048];    // 16 MB

// ---------------------------------------------------------------------------
__device__ __forceinline__ uint32_t smem_u32(const void* p) {
    uint32_t a;
    asm("{ .reg .u64 t; cvta.to.shared.u64 t, %1; cvt.u32.u64 %0, t; }" : "=r"(a) : "l"(p));
    return a;
}

__device__ __forceinline__ void cp16(uint32_t dst, const void* src) {
    asm volatile("cp.async.cg.shared.global [%0], [%1], 16;"
                 :: "r"(dst), "l"(src) : "memory");
}
#define CP_COMMIT() asm volatile("cp.async.commit_group;" ::: "memory")
#define CP_WAIT1()  asm volatile("cp.async.wait_group 1;"  ::: "memory")
#define CP_WAIT2()  asm volatile("cp.async.wait_group 2;"  ::: "memory")

__device__ __forceinline__ uint32_t f2tf(float f) {
    uint32_t r;
    asm("cvt.rna.tf32.f32 %0, %1;" : "=r"(r) : "f"(f));
    return r;
}

__device__ __forceinline__ void mma_tf32(float c[4],
                                         const uint32_t a[4], const uint32_t b[2]) {
    asm volatile(
        "mma.sync.aligned.m16n8k8.row.col.f32.tf32.tf32.f32 "
        "{%0,%1,%2,%3}, {%4,%5,%6,%7}, {%8,%9}, {%0,%1,%2,%3};"
        : "+f"(c[0]), "+f"(c[1]), "+f"(c[2]), "+f"(c[3])
        : "r"(a[0]), "r"(a[1]), "r"(a[2]), "r"(a[3]), "r"(b[0]), "r"(b[1]));
}

// ---------------------------------------------------------------------------
// Fused pack kernel. Fragment-major layouts:
//   A chunk ((wm*4+t)*4+ks)*32+lane -> 16B quad {A[r,c],A[r+8,c],A[r,c+4],A[r+8,c+4]}
//   B chunk ((wn*8+u)*4+ks)*32+lane -> 8B pair {B[n,c],B[n,c+4]}, n>=1000 zeroed
// Each thread handles 4 consecutive kt. Blocks [0,4096): A. [4096,6144): B.
// ---------------------------------------------------------------------------
__global__ void __launch_bounds__(256) pack_ab_kernel(const float* __restrict__ A,
                                                      const float* __restrict__ B) {
    const uint32_t bid = blockIdx.x;
    const uint32_t tidl = threadIdx.x;
    if (bid < 4096) {
        const uint32_t idx = bid * 256u + tidl;        // [0, 2^20)
        const uint32_t mtile = idx >> 16;
        const uint32_t ktg   = (idx >> 11) & 31u;
        const uint32_t chunk = idx & 2047u;
        const uint32_t lane  = chunk & 31u;
        const uint32_t blk   = chunk >> 5;
        const uint32_t ks    = blk & 3u;
        const uint32_t t     = (blk >> 2) & 3u;
        const uint32_t wm    = blk >> 4;
        const uint32_t r = mtile * 256 + wm * 64 + t * 16 + (lane >> 2);
        const float* rowp = A + (size_t)r * KDIM;
        #pragma unroll
        for (int j = 0; j < 4; j++) {
            const uint32_t kt = ktg * 4 + j;
            const uint32_t c  = kt * 32 + ks * 8 + (lane & 3);
            const float* p = rowp + c;
            uint4 v;
            v.x = f2tf(p[0]);
            v.y = f2tf(p[(size_t)8 * KDIM]);
            v.z = f2tf(p[4]);
            v.w = f2tf(p[(size_t)8 * KDIM + 4]);
            g_Ap[(size_t)(mtile * 128 + kt) * 2048 + chunk] = v;
        }
    } else {
        const uint32_t idx = (bid - 4096u) * 256u + tidl;  // [0, 2^19)
        const uint32_t ntile = idx >> 16;
        const uint32_t ktg   = (idx >> 11) & 31u;
        const uint32_t chunk = idx & 2047u;
        const uint32_t lane  = chunk & 31u;
        const uint32_t blk   = chunk >> 5;
        const uint32_t ks    = blk & 3u;
        const uint32_t u     = (blk >> 2) & 7u;
        const uint32_t wn    = blk >> 5;
        const uint32_t n = ntile * 128 + wn * 64 + u * 8 + (lane >> 2);
        const float* rowp = B + (size_t)n * KDIM;
        #pragma unroll
        for (int j = 0; j < 4; j++) {
            const uint32_t kt = ktg * 4 + j;
            const uint32_t c  = kt * 32 + ks * 8 + (lane & 3);
            uint2 v = make_uint2(0u, 0u);
            if (n < NDIM) {
                const float* p = rowp + c;
                v.x = f2tf(p[0]);
                v.y = f2tf(p[4]);
            }
            g_Bp[(size_t)(ntile * 128 + kt) * 2048 + chunk] = v;
        }
    }
}

// ---------------------------------------------------------------------------
// GEMM: R7 structure verbatim.
// ---------------------------------------------------------------------------
__global__ void __launch_bounds__(THREADS, 1)
tol_gemm_tf32(float* __restrict__ C) {         // [4096, 1000]
    extern __shared__ char smem[];
    const int tid  = threadIdx.x;
    const int wid  = tid >> 5;
    const int lane = tid & 31;

    const int mtile = blockIdx.y;
    const int ntile = blockIdx.x;
    const int m0 = mtile * BM;
    const int n0 = ntile * BN;

    const int warp_m = wid >> 1;     // 0..3
    const int warp_n = wid & 1;      // 0..1

    const uint32_t sb = smem_u32(smem);

#define ISSUE_STAGE(kt_, s_) do {                                                \
        const uint32_t soff = (uint32_t)(s_) * STAGE_BYTES;                      \
        const uint4* asrc = g_Ap + ((size_t)(mtile * KTILES + (kt_))) * 2048;    \
        const uint2* bsrc = g_Bp + ((size_t)(ntile * KTILES + (kt_))) * 2048;    \
        _Pragma("unroll")                                                        \
        for (int i = 0; i < 8; i++)                                              \
            cp16(sb + soff + (uint32_t)(tid + i * 256) * 16,                     \
                 asrc + tid + i * 256);                                          \
        _Pragma("unroll")                                                        \
        for (int i = 0; i < 4; i++)                                              \
            cp16(sb + soff + A_TILE_BYTES + (uint32_t)(tid + i * 256) * 16,      \
                 bsrc + (tid + i * 256) * 2);                                    \
    } while (0)

    float acc[4][8][4];
    #pragma unroll
    for (int t = 0; t < 4; t++)
        #pragma unroll
        for (int u = 0; u < 8; u++)
            #pragma unroll
            for (int i = 0; i < 4; i++)
                acc[t][u][i] = 0.0f;

    // prologue: fill STAGES-1 = 3 stages
    #pragma unroll
    for (int p = 0; p < STAGES - 1; p++) {
        ISSUE_STAGE(p, p);
        CP_COMMIT();
    }

    // fragment double buffers
    uint32_t af[2][4][4];
    uint32_t bf[2][8][2];

#define LOAD_FRAG(buf, aS, bS, ksv) do {                                         \
        _Pragma("unroll")                                                        \
        for (int t = 0; t < 4; t++) {                                            \
            uint4 v = (aS)[((warp_m * 4 + t) * 4 + (ksv)) * 32 + lane];          \
            af[buf][t][0] = v.x; af[buf][t][1] = v.y;                            \
            af[buf][t][2] = v.z; af[buf][t][3] = v.w;                            \
        }                                                                        \
        _Pragma("unroll")                                                        \
        for (int u = 0; u < 8; u++) {                                            \
            uint2 w = (bS)[((warp_n * 8 + u) * 4 + (ksv)) * 32 + lane];          \
            bf[buf][u][0] = w.x; bf[buf][u][1] = w.y;                            \
        }                                                                        \
    } while (0)

#define MMA_ALL(buf) do {                                                        \
        _Pragma("unroll")                                                        \
        for (int t = 0; t < 4; t++)                                              \
            _Pragma("unroll")                                                    \
            for (int u = 0; u < 8; u++)                                          \
                mma_tf32(acc[t][u], af[buf][t], bf[buf][u]);                     \
    } while (0)

#define STAGE_A(s_) reinterpret_cast<const uint4*>(smem + (s_) * STAGE_BYTES)
#define STAGE_B(s_) reinterpret_cast<const uint2*>(smem + (s_) * STAGE_BYTES + A_TILE_BYTES)

    // preload buf0 = frag(kt=0, ks=0) from stage 0
    CP_WAIT2();
    __syncthreads();
    LOAD_FRAG(0, STAGE_A(0), STAGE_B(0), 0);

    // One pipeline phase at compile-time stage S. Enters with buf0 holding
    // frag(kt, ks=0); exits with buf0 holding frag(kt+1, ks=0) read from the
    // NEXT stage (complete per wait_group 1; not overwritten until the kt+2
    // refill, which is behind the kt+2 barrier).
#define PHASE(S, kt_) do {                                                       \
        CP_WAIT1();                                                              \
        __syncthreads();                                                         \
        const int kn = (kt_) + STAGES - 1;                                       \
        if (kn < KTILES) ISSUE_STAGE(kn, ((S) + STAGES - 1) & 3);                \
        CP_COMMIT();                                                             \
        const uint4* aS = STAGE_A(S);                                            \
        const uint2* bS = STAGE_B(S);                                            \
        const uint4* aN = STAGE_A(((S) + 1) & 3);                                \
        const uint2* bN = STAGE_B(((S) + 1) & 3);                                \
        LOAD_FRAG(1, aS, bS, 1);  MMA_ALL(0);                                    \
        LOAD_FRAG(0, aS, bS, 2);  MMA_ALL(1);                                    \
        LOAD_FRAG(1, aS, bS, 3);  MMA_ALL(0);                                    \
        LOAD_FRAG(0, aN, bN, 0);  MMA_ALL(1);                                    \
    } while (0)

    for (int kt = 0; kt < KTILES; kt += 4) {
        PHASE(0, kt);
        PHASE(1, kt + 1);
        PHASE(2, kt + 2);
        PHASE(3, kt + 3);
    }

    // ---- epilogue: each warp writes its 64x64 region, guard N edge ----
    #pragma unroll
    for (int t = 0; t < 4; t++) {
        const int gr = m0 + warp_m * 64 + t * 16 + (lane >> 2);
        #pragma unroll
        for (int u = 0; u < 8; u++) {
            const int gc = n0 + warp_n * 64 + u * 8 + (lane & 3) * 2;
            if (gc < NDIM) {   // NDIM even; float2 never straddles the edge
                float2 v0 = make_float2(acc[t][u][0], acc[t][u][1]);
                float2 v1 = make_float2(acc[t][u][2], acc[t][u][3]);
                *reinterpret_cast<float2*>(C + (size_t)gr * NDIM + gc) = v0;
                *reinterpret_cast<float2*>(C + (size_t)(gr + 8) * NDIM + gc) = v1;
            }
        }
    }
}

// ---------------------------------------------------------------------------
extern "C" void kernel_launch(void* const* d_in, const int* in_sizes, int n_in,
                              void* d_out, int out_size) {
    const float* core = (const float*)d_in[0];   // [4096, 16,16,16] = [4096,4096]
    const float* wts  = (const float*)d_in[1];   // [1000, 4096]
    float* out = (float*)d_out;                  // [4096, 1000]

    // fused pack prepass (same stream -> ordered before GEMM)
    pack_ab_kernel<<<6144, 256>>>(core, wts);

    cudaFuncSetAttribute(tol_gemm_tf32,
                         cudaFuncAttributeMaxDynamicSharedMemorySize, SMEM_BYTES);

    dim3 grid(8, 16, 1);   // 128 CTAs = 1 clean wave
    tol_gemm_tf32<<<grid, THREADS, SMEM_BYTES>>>(out);
}

// round 13
// speedup vs baseline: 1.7004x; 1.1050x over previous
#include <cuda_runtime.h>
#include <cstdint>

// ============================================================================
// out[4096,1000] = core[4096,4096] @ weights[1000,4096]^T   (fp32)
//
// R13 vs R12 (174.8us; GEMM 149.6 @ tensor 75.6%): use the idle 20 SMs.
// BN 128 -> 112 (9 ntiles cover 1008>=1000) => grid 9x16 = 144 CTAs = one
// clean wave on 148 SMs; per-SM tensor floor drops 12.5%. Warp tile 64x56,
// B stage 14KB. Pipeline structure identical to R12 (per-kt commit groups,
// per-kt barrier, 4-stage cp.async, cross-phase ks0 prefetch).
// ============================================================================

#define MDIM 4096
#define NDIM 1000
#define KDIM 4096

#define BM 256
#define BN 112
#define NTILES 9                      // 9*112 = 1008 >= 1000
#define BK 32
#define KTILES (KDIM / BK)            // 128
#define STAGES 4
#define THREADS 256
#define NU 7                          // u-extent per warp (56 cols / 8)

#define A_TILE_BYTES (BM * BK * 4)    // 32768
#define CHB (2 * NU * 4 * 32)         // B uint2-chunks per kt = 1792
#define B_TILE_BYTES (CHB * 8)        // 14336
#define STAGE_BYTES  (A_TILE_BYTES + B_TILE_BYTES)   // 47104
#define SMEM_BYTES   (STAGES * STAGE_BYTES)          // 188416

// packed scratch:
//   A' = [16 mtiles][128 kt][2048 x 16B]  (unchanged layout)
//   B' = [ 9 ntiles][128 kt][1792 x  8B]
__device__ uint4 g_Ap[16 * 128 * 2048];        // 64 MB
__device__ uint2 g_Bp[NTILES * 128 * CHB];     // ~16.5 MB

// ---------------------------------------------------------------------------
__device__ __forceinline__ uint32_t smem_u32(const void* p) {
    uint32_t a;
    asm("{ .reg .u64 t; cvta.to.shared.u64 t, %1; cvt.u32.u64 %0, t; }" : "=r"(a) : "l"(p));
    return a;
}

__device__ __forceinline__ void cp16(uint32_t dst, const void* src) {
    asm volatile("cp.async.cg.shared.global [%0], [%1], 16;"
                 :: "r"(dst), "l"(src) : "memory");
}
#define CP_COMMIT() asm volatile("cp.async.commit_group;" ::: "memory")
#define CP_WAIT1()  asm volatile("cp.async.wait_group 1;"  ::: "memory")
#define CP_WAIT2()  asm volatile("cp.async.wait_group 2;"  ::: "memory")

__device__ __forceinline__ uint32_t f2tf(float f) {
    uint32_t r;
    asm("cvt.rna.tf32.f32 %0, %1;" : "=r"(r) : "f"(f));
    return r;
}

__device__ __forceinline__ void mma_tf32(float c[4],
                                         const uint32_t a[4], const uint32_t b[2]) {
    asm volatile(
        "mma.sync.aligned.m16n8k8.row.col.f32.tf32.tf32.f32 "
        "{%0,%1,%2,%3}, {%4,%5,%6,%7}, {%8,%9}, {%0,%1,%2,%3};"
        : "+f"(c[0]), "+f"(c[1]), "+f"(c[2]), "+f"(c[3])
        : "r"(a[0]), "r"(a[1]), "r"(a[2]), "r"(a[3]), "r"(b[0]), "r"(b[1]));
}

// ---------------------------------------------------------------------------
// Fused pack kernel.
//   A chunk ((wm*4+t)*4+ks)*32+lane -> 16B quad {A[r,c],A[r+8,c],A[r,c+4],A[r+8,c+4]}
//   B chunk ((wn*7+u)*4+ks)*32+lane -> 8B pair {B[n,c],B[n,c+4]}, n>=1000 zeroed
//     n = ntile*112 + wn*56 + u*8 + (lane>>2)
// Blocks [0,4096): A (4 kt per thread). Blocks [4096,6112): B (1 chunk/thread,
// 9*32*1792/256 = 2016 blocks, 4 kt per thread via ktg).
// ---------------------------------------------------------------------------
__global__ void __launch_bounds__(256) pack_ab_kernel(const float* __restrict__ A,
                                                      const float* __restrict__ B) {
    const uint32_t bid = blockIdx.x;
    const uint32_t tidl = threadIdx.x;
    if (bid < 4096) {
        const uint32_t idx = bid * 256u + tidl;        // [0, 2^20)
        const uint32_t mtile = idx >> 16;
        const uint32_t ktg   = (idx >> 11) & 31u;
        const uint32_t chunk = idx & 2047u;
        const uint32_t lane  = chunk & 31u;
        const uint32_t blk   = chunk >> 5;
        const uint32_t ks    = blk & 3u;
        const uint32_t t     = (blk >> 2) & 3u;
        const uint32_t wm    = blk >> 4;
        const uint32_t r = mtile * 256 + wm * 64 + t * 16 + (lane >> 2);
        const float* rowp = A + (size_t)r * KDIM;
        #pragma unroll
        for (int j = 0; j < 4; j++) {
            const uint32_t kt = ktg * 4 + j;
            const uint32_t c  = kt * 32 + ks * 8 + (lane & 3);
            const float* p = rowp + c;
            uint4 v;
            v.x = f2tf(p[0]);
            v.y = f2tf(p[(size_t)8 * KDIM]);
            v.z = f2tf(p[4]);
            v.w = f2tf(p[(size_t)8 * KDIM + 4]);
            g_Ap[(size_t)(mtile * 128 + kt) * 2048 + chunk] = v;
        }
    } else {
        const uint32_t idx = (bid - 4096u) * 256u + tidl;   // [0, 516096)
        const uint32_t chunk = idx % CHB;                   // 0..1791
        const uint32_t rest  = idx / CHB;
        const uint32_t ktg   = rest & 31u;                  // 32 kt-groups of 4
        const uint32_t ntile = rest >> 5;                   // 0..8
        const uint32_t lane  = chunk & 31u;
        const uint32_t blk   = chunk >> 5;                  // 0..55
        const uint32_t ks    = blk & 3u;
        const uint32_t uw    = blk >> 2;                    // 0..13 = wn*7+u
        const uint32_t u     = uw % NU;
        const uint32_t wn    = uw / NU;
        const uint32_t n = ntile * BN + wn * 56 + u * 8 + (lane >> 2);
        const float* rowp = B + (size_t)n * KDIM;
        #pragma unroll
        for (int j = 0; j < 4; j++) {
            const uint32_t kt = ktg * 4 + j;
            const uint32_t c  = kt * 32 + ks * 8 + (lane & 3);
            uint2 v = make_uint2(0u, 0u);
            if (n < NDIM) {
                const float* p = rowp + c;
                v.x = f2tf(p[0]);
                v.y = f2tf(p[4]);
            }
            g_Bp[(size_t)(ntile * 128 + kt) * CHB + chunk] = v;
        }
    }
}

// ---------------------------------------------------------------------------
// GEMM: R7/R12 structure; BN=112, warp tile 64x56.
// ---------------------------------------------------------------------------
__global__ void __launch_bounds__(THREADS, 1)
tol_gemm_tf32(float* __restrict__ C) {         // [4096, 1000]
    extern __shared__ char smem[];
    const int tid  = threadIdx.x;
    const int wid  = tid >> 5;
    const int lane = tid & 31;

    const int mtile = blockIdx.y;
    const int ntile = blockIdx.x;
    const int m0 = mtile * BM;
    const int n0 = ntile * BN;

    const int warp_m = wid >> 1;     // 0..3
    const int warp_n = wid & 1;      // 0..1

    const uint32_t sb = smem_u32(smem);

    // B tile per kt = 1792 uint2 = 896 x 16B chunks; 256 threads: 3 each + 128 extra
#define ISSUE_STAGE(kt_, s_) do {                                                \
        const uint32_t soff = (uint32_t)(s_) * STAGE_BYTES;                      \
        const uint4* asrc = g_Ap + ((size_t)(mtile * KTILES + (kt_))) * 2048;    \
        const uint2* bsrc = g_Bp + ((size_t)(ntile * KTILES + (kt_))) * CHB;     \
        _Pragma("unroll")                                                        \
        for (int i = 0; i < 8; i++)                                              \
            cp16(sb + soff + (uint32_t)(tid + i * 256) * 16,                     \
                 asrc + tid + i * 256);                                          \
        _Pragma("unroll")                                                        \
        for (int i = 0; i < 3; i++)                                              \
            cp16(sb + soff + A_TILE_BYTES + (uint32_t)(tid + i * 256) * 16,      \
                 bsrc + (tid + i * 256) * 2);                                    \
        if (tid < 128)                                                           \
            cp16(sb + soff + A_TILE_BYTES + (uint32_t)(tid + 768) * 16,          \
                 bsrc + (tid + 768) * 2);                                        \
    } while (0)

    float acc[4][NU][4];
    #pragma unroll
    for (int t = 0; t < 4; t++)
        #pragma unroll
        for (int u = 0; u < NU; u++)
            #pragma unroll
            for (int i = 0; i < 4; i++)
                acc[t][u][i] = 0.0f;

    // prologue: fill STAGES-1 = 3 stages
    #pragma unroll
    for (int p = 0; p < STAGES - 1; p++) {
        ISSUE_STAGE(p, p);
        CP_COMMIT();
    }

    // fragment double buffers
    uint32_t af[2][4][4];
    uint32_t bf[2][NU][2];

#define LOAD_FRAG(buf, aS, bS, ksv) do {                                         \
        _Pragma("unroll")                                                        \
        for (int t = 0; t < 4; t++) {                                            \
            uint4 v = (aS)[((warp_m * 4 + t) * 4 + (ksv)) * 32 + lane];          \
            af[buf][t][0] = v.x; af[buf][t][1] = v.y;                            \
            af[buf][t][2] = v.z; af[buf][t][3] = v.w;                            \
        }                                                                        \
        _Pragma("unroll")                                                        \
        for (int u = 0; u < NU; u++) {                                           \
            uint2 w = (bS)[((warp_n * NU + u) * 4 + (ksv)) * 32 + lane];         \
            bf[buf][u][0] = w.x; bf[buf][u][1] = w.y;                            \
        }                                                                        \
    } while (0)

#define MMA_ALL(buf) do {                                                        \
        _Pragma("unroll")                                                        \
        for (int t = 0; t < 4; t++)                                              \
            _Pragma("unroll")                                                    \
            for (int u = 0; u < NU; u++)                                         \
                mma_tf32(acc[t][u], af[buf][t], bf[buf][u]);                     \
    } while (0)

#define STAGE_A(s_) reinterpret_cast<const uint4*>(smem + (s_) * STAGE_BYTES)
#define STAGE_B(s_) reinterpret_cast<const uint2*>(smem + (s_) * STAGE_BYTES + A_TILE_BYTES)

    // preload buf0 = frag(kt=0, ks=0) from stage 0
    CP_WAIT2();
    __syncthreads();
    LOAD_FRAG(0, STAGE_A(0), STAGE_B(0), 0);

#define PHASE(S, kt_) do {                                                       \
        CP_WAIT1();                                                              \
        __syncthreads();                                                         \
        const int kn = (kt_) + STAGES - 1;                                       \
        if (kn < KTILES) ISSUE_STAGE(kn, ((S) + STAGES - 1) & 3);                \
        CP_COMMIT();                                                             \
        const uint4* aS = STAGE_A(S);                                            \
        const uint2* bS = STAGE_B(S);                                            \
        const uint4* aN = STAGE_A(((S) + 1) & 3);                                \
        const uint2* bN = STAGE_B(((S) + 1) & 3);                                \
        LOAD_FRAG(1, aS, bS, 1);  MMA_ALL(0);                                    \
        LOAD_FRAG(0, aS, bS, 2);  MMA_ALL(1);                                    \
        LOAD_FRAG(1, aS, bS, 3);  MMA_ALL(0);                                    \
        LOAD_FRAG(0, aN, bN, 0);  MMA_ALL(1);                                    \
    } while (0)

    for (int kt = 0; kt < KTILES; kt += 4) {
        PHASE(0, kt);
        PHASE(1, kt + 1);
        PHASE(2, kt + 2);
        PHASE(3, kt + 3);
    }

    // ---- epilogue: each warp writes its 64x56 region, guard N edge ----
    #pragma unroll
    for (int t = 0; t < 4; t++) {
        const int gr = m0 + warp_m * 64 + t * 16 + (lane >> 2);
        #pragma unroll
        for (int u = 0; u < NU; u++) {
            const int gc = n0 + warp_n * 56 + u * 8 + (lane & 3) * 2;
            if (gc < NDIM) {   // NDIM even; float2 never straddles the edge
                float2 v0 = make_float2(acc[t][u][0], acc[t][u][1]);
                float2 v1 = make_float2(acc[t][u][2], acc[t][u][3]);
                *reinterpret_cast<float2*>(C + (size_t)gr * NDIM + gc) = v0;
                *reinterpret_cast<float2*>(C + (size_t)(gr + 8) * NDIM + gc) = v1;
            }
        }
    }
}

// ---------------------------------------------------------------------------
extern "C" void kernel_launch(void* const* d_in, const int* in_sizes, int n_in,
                              void* d_out, int out_size) {
    const float* core = (const float*)d_in[0];   // [4096, 16,16,16] = [4096,4096]
    const float* wts  = (const float*)d_in[1];   // [1000, 4096]
    float* out = (float*)d_out;                  // [4096, 1000]

    // fused pack prepass: 4096 A-blocks + 2016 B-blocks
    pack_ab_kernel<<<6112, 256>>>(core, wts);

    cudaFuncSetAttribute(tol_gemm_tf32,
                         cudaFuncAttributeMaxDynamicSharedMemorySize, SMEM_BYTES);

    dim3 grid(NTILES, 16, 1);   // 9 x 16 = 144 CTAs = one wave on 148 SMs
    tol_gemm_tf32<<<grid, THREADS, SMEM_BYTES>>>(out);
}